// round 8
// baseline (speedup 1.0000x reference)
#include <cuda_runtime.h>
#include <cuda_bf16.h>
#include <math_constants.h>
#include <cstdint>

#define B_ 4
#define C_ 128
#define N_ 4096
#define TQ 128           // queries per CTA
#define TK 64            // keys per iteration
#define NT (N_ / TK)     // 64 iterations

// bf16 hi/lo scratch, all token-major [B][N][C]
__device__ __nv_bfloat16 g_qh[B_*N_*C_], g_ql[B_*N_*C_];
__device__ __nv_bfloat16 g_kh[B_*N_*C_], g_kl[B_*N_*C_];
__device__ __nv_bfloat16 g_vh[B_*N_*C_], g_vl[B_*N_*C_];

// ---------------- helpers ----------------
__device__ __forceinline__ uint32_t smem_u32(const void* p) {
    uint32_t a;
    asm("{ .reg .u64 t; cvta.to.shared.u64 t, %1; cvt.u32.u64 %0, t; }"
        : "=r"(a) : "l"(p));
    return a;
}
__device__ __forceinline__ void cpa16(uint32_t dst, const void* src) {
    asm volatile("cp.async.cg.shared.global [%0], [%1], 16;" :: "r"(dst), "l"(src));
}
__device__ __forceinline__ void cpa_commit() {
    asm volatile("cp.async.commit_group;" ::: "memory");
}
template<int NG> __device__ __forceinline__ void cpa_wait() {
    asm volatile("cp.async.wait_group %0;" :: "n"(NG) : "memory");
}
__device__ __forceinline__ void ldsm4(uint32_t* r, uint32_t a) {
    asm volatile("ldmatrix.sync.aligned.m8n8.x4.shared.b16 {%0,%1,%2,%3}, [%4];"
                 : "=r"(r[0]), "=r"(r[1]), "=r"(r[2]), "=r"(r[3]) : "r"(a));
}
__device__ __forceinline__ void ldsm4t(uint32_t* r, uint32_t a) {
    asm volatile("ldmatrix.sync.aligned.m8n8.x4.trans.shared.b16 {%0,%1,%2,%3}, [%4];"
                 : "=r"(r[0]), "=r"(r[1]), "=r"(r[2]), "=r"(r[3]) : "r"(a));
}
__device__ __forceinline__ void mma16816(float* d, const uint32_t* a,
                                         const uint32_t* b) {
    asm volatile(
        "mma.sync.aligned.m16n8k16.row.col.f32.bf16.bf16.f32 "
        "{%0,%1,%2,%3}, {%4,%5,%6,%7}, {%8,%9}, {%0,%1,%2,%3};"
        : "+f"(d[0]), "+f"(d[1]), "+f"(d[2]), "+f"(d[3])
        : "r"(a[0]), "r"(a[1]), "r"(a[2]), "r"(a[3]), "r"(b[0]), "r"(b[1]));
}
__device__ __forceinline__ uint32_t pack_bf16(float lo, float hi) {
    uint32_t ul = (uint32_t)__bfloat16_as_ushort(__float2bfloat16_rn(lo));
    uint32_t uh = (uint32_t)__bfloat16_as_ushort(__float2bfloat16_rn(hi));
    return (uh << 16) | ul;
}
// smem row = 256 B (128 bf16). 16B-chunk XOR swizzle: conflict-free ldmatrix.
__device__ __forceinline__ uint32_t swadr(uint32_t base, int row, int chunk) {
    return base + row * 256 + ((chunk ^ (row & 7)) << 4);
}

// SMEM (bytes): QH 0..32K, QL 32K..64K
// K slot s: 64K + s*32K  (KH +0, KL +16K)
// V slot s: 128K + s*32K (VH +0, VL +16K)
#define OFF_K(s) (65536 + (s) * 32768)
#define OFF_V(s) (131072 + (s) * 32768)
#define SMEM_ATTN 196608

// ---------------------------------------------------------------------------
// QKV projection (fp32 SIMT GEMM) -> bf16 hi/lo token-major [B][N][C]
// ---------------------------------------------------------------------------
__global__ __launch_bounds__(256) void qkv_kernel(
    const float* __restrict__ x,
    const float* __restrict__ wq, const float* __restrict__ bq,
    const float* __restrict__ wk, const float* __restrict__ bk,
    const float* __restrict__ wv, const float* __restrict__ bv)
{
    extern __shared__ float sm[];
    float* Xs = sm;          // 128*64
    float* Ws = sm + 8192;   // 64*128

    const int tid = threadIdx.x;
    const int tx = tid & 15, ty = tid >> 4;
    const int ntile = blockIdx.x, otile = blockIdx.y, b = blockIdx.z;

    const float* w; const float* bias;
    __nv_bfloat16 *oh, *ol;
    if (otile < 2)      { w = wq; bias = bq; oh = g_qh; ol = g_ql; }
    else if (otile < 4) { w = wk; bias = bk; oh = g_kh; ol = g_kl; }
    else                { w = wv; bias = bv; oh = g_vh; ol = g_vl; }
    const int orow0 = (otile & 1) * 64;
    const int n0 = ntile * 64;

    #pragma unroll
    for (int p = 0; p < 32; p++) {
        int idx = tid + p * 256;
        Ws[idx] = w[(orow0 + (idx >> 7)) * C_ + (idx & 127)];
    }
    #pragma unroll
    for (int p = 0; p < 32; p++) {
        int idx = tid + p * 256;
        Xs[idx] = x[(b * C_ + (idx >> 6)) * N_ + n0 + (idx & 63)];
    }
    __syncthreads();

    float acc[4][4];
    #pragma unroll
    for (int i = 0; i < 4; i++)
        #pragma unroll
        for (int j = 0; j < 4; j++) acc[i][j] = 0.f;

    #pragma unroll 8
    for (int c = 0; c < 128; c++) {
        float4 xf = *(const float4*)&Xs[c * 64 + tx * 4];
        #pragma unroll
        for (int i = 0; i < 4; i++) {
            float wf = Ws[(ty * 4 + i) * 128 + c];
            acc[i][0] += wf * xf.x; acc[i][1] += wf * xf.y;
            acc[i][2] += wf * xf.z; acc[i][3] += wf * xf.w;
        }
    }

    float bb[4];
    #pragma unroll
    for (int i = 0; i < 4; i++) bb[i] = bias[orow0 + ty * 4 + i];

    #pragma unroll
    for (int j = 0; j < 4; j++) {
        int n = n0 + tx * 4 + j;
        __nv_bfloat16 h[4], l[4];
        #pragma unroll
        for (int i = 0; i < 4; i++) {
            float v = acc[i][j] + bb[i];
            h[i] = __float2bfloat16_rn(v);
            l[i] = __float2bfloat16_rn(v - __bfloat162float(h[i]));
        }
        size_t base = (size_t)(b * N_ + n) * C_ + orow0 + ty * 4;
        *(uint2*)&oh[base] = *(uint2*)h;
        *(uint2*)&ol[base] = *(uint2*)l;
    }
}

// ---- macro blocks for the attention mainloop ----
#define LOAD_K(slot, k0) do {                                                  \
    _Pragma("unroll")                                                          \
    for (int i_ = 0; i_ < 4; i_++) {                                           \
        int idx_ = tid + i_ * 256;                                             \
        int row_ = idx_ >> 4, ch_ = idx_ & 15;                                 \
        uint32_t dst_ = swadr(sb + OFF_K(slot), row_, ch_);                    \
        size_t g_ = ((size_t)(b * N_ + (k0) + row_) * C_) * 2 + ch_ * 16;      \
        cpa16(dst_,         (const char*)g_kh + g_);                           \
        cpa16(dst_ + 16384, (const char*)g_kl + g_);                           \
    } } while (0)

#define LOAD_V(slot, k0) do {                                                  \
    _Pragma("unroll")                                                          \
    for (int i_ = 0; i_ < 4; i_++) {                                           \
        int idx_ = tid + i_ * 256;                                             \
        int row_ = idx_ >> 4, ch_ = idx_ & 15;                                 \
        uint32_t dst_ = swadr(sb + OFF_V(slot), row_, ch_);                    \
        size_t g_ = ((size_t)(b * N_ + (k0) + row_) * C_) * 2 + ch_ * 16;      \
        cpa16(dst_,         (const char*)g_vh + g_);                           \
        cpa16(dst_ + 16384, (const char*)g_vl + g_);                           \
    } } while (0)

// one ks-slab (k-depth 16) of S(t+1): 8 ldsm + 24 MMA
#define S_KS_BLOCK(ks, kb) do {                                                \
    uint32_t qh4_[4], ql4_[4];                                                 \
    uint32_t qa_ = swadr(sb, w * 16 + (lane & 15), (ks) * 2 + (lane >> 4));    \
    ldsm4(qh4_, qa_); ldsm4(ql4_, qa_ + 32768);                                \
    _Pragma("unroll")                                                          \
    for (int np_ = 0; np_ < 4; np_++) {                                        \
        uint32_t khp_[4], klp_[4];                                             \
        int krow_ = (2 * np_ + (lane >> 4)) * 8 + (lane & 7);                  \
        int kch_ = (ks) * 2 + ((lane >> 3) & 1);                               \
        uint32_t ka_ = swadr((kb), krow_, kch_);                               \
        ldsm4(khp_, ka_); ldsm4(klp_, ka_ + 16384);                            \
        mma16816(sacc[2*np_],   qh4_, khp_);                                   \
        mma16816(sacc[2*np_+1], qh4_, khp_ + 2);                               \
        mma16816(sacc[2*np_],   qh4_, klp_);                                   \
        mma16816(sacc[2*np_+1], qh4_, klp_ + 2);                               \
        mma16816(sacc[2*np_],   ql4_, khp_);                                   \
        mma16816(sacc[2*np_+1], ql4_, khp_ + 2);                               \
    } } while (0)

// half of PV chunk kk (np range h*4..h*4+4): 8 ldsm + 24 MMA
#define PV_PIECE(vb, kk, h) do {                                               \
    _Pragma("unroll")                                                          \
    for (int np_ = (h) * 4; np_ < (h) * 4 + 4; np_++) {                        \
        uint32_t vhf_[4], vlf_[4];                                             \
        uint32_t va_ = swadr((vb), (kk) * 16 + (lane & 15),                    \
                             2 * np_ + (lane >> 4));                           \
        ldsm4t(vhf_, va_); ldsm4t(vlf_, va_ + 16384);                          \
        mma16816(oacc[2*np_],   ph[(kk)], vhf_);                               \
        mma16816(oacc[2*np_+1], ph[(kk)], vhf_ + 2);                           \
        mma16816(oacc[2*np_],   ph[(kk)], vlf_);                               \
        mma16816(oacc[2*np_+1], ph[(kk)], vlf_ + 2);                           \
        mma16816(oacc[2*np_],   pl[(kk)], vhf_);                               \
        mma16816(oacc[2*np_+1], pl[(kk)], vhf_ + 2);                           \
    } } while (0)

// softmax of the tile in sacc -> ph/pl (all 4 chunks), accumulate lr
#define SOFTMAX_ALL() do {                                                     \
    _Pragma("unroll")                                                          \
    for (int kk_ = 0; kk_ < 4; kk_++) {                                        \
        _Pragma("unroll")                                                      \
        for (int hf_ = 0; hf_ < 2; hf_++) {                                    \
            int n_ = 2 * kk_ + hf_;                                            \
            float p0_ = __expf(sacc[n_][0] - m0r0);                            \
            float p1_ = __expf(sacc[n_][1] - m0r0);                            \
            float p2_ = __expf(sacc[n_][2] - m0r1);                            \
            float p3_ = __expf(sacc[n_][3] - m0r1);                            \
            lr0 += p0_ + p1_; lr1 += p2_ + p3_;                                \
            uint32_t h01_ = pack_bf16(p0_, p1_);                               \
            uint32_t h23_ = pack_bf16(p2_, p3_);                               \
            float h0_ = __bfloat162float(__ushort_as_bfloat16((unsigned short)(h01_ & 0xffff))); \
            float h1_ = __bfloat162float(__ushort_as_bfloat16((unsigned short)(h01_ >> 16)));    \
            float h2_ = __bfloat162float(__ushort_as_bfloat16((unsigned short)(h23_ & 0xffff))); \
            float h3_ = __bfloat162float(__ushort_as_bfloat16((unsigned short)(h23_ >> 16)));    \
            ph[kk_][hf_ * 2]     = h01_;                                       \
            ph[kk_][hf_ * 2 + 1] = h23_;                                       \
            pl[kk_][hf_ * 2]     = pack_bf16(p0_ - h0_, p1_ - h1_);            \
            pl[kk_][hf_ * 2 + 1] = pack_bf16(p2_ - h2_, p3_ - h3_);            \
        } } } while (0)

#define ZERO_SACC() do {                                                       \
    _Pragma("unroll")                                                          \
    for (int n_ = 0; n_ < 8; n_++) {                                           \
        sacc[n_][0] = 0.f; sacc[n_][1] = 0.f;                                  \
        sacc[n_][2] = 0.f; sacc[n_][3] = 0.f;                                  \
    } } while (0)

// ---------------------------------------------------------------------------
// mma.sync flash attention, bf16x3, cross-iteration pipelined:
// each phase interleaves PV(t) with S(t+1). Grid (N/128, B), 256 threads.
// ---------------------------------------------------------------------------
__global__ __launch_bounds__(256, 1) void attn_kernel(float* __restrict__ out)
{
    extern __shared__ char smem[];
    const uint32_t sb = smem_u32(smem);
    const int tid = threadIdx.x;
    const int w = tid >> 5, lane = tid & 31;
    const int b = blockIdx.y;
    const int q0 = blockIdx.x * TQ;

    // ---- prologue: {Q, K0} | {K1, V0} as two cp.async groups ----
    #pragma unroll
    for (int i = 0; i < 8; i++) {
        int idx = tid + i * 256;              // 2048 chunks (128 rows x 16)
        int row = idx >> 4, ch = idx & 15;
        uint32_t dst = swadr(sb, row, ch);
        size_t g = ((size_t)(b * N_ + q0 + row) * C_) * 2 + ch * 16;
        cpa16(dst, (const char*)g_qh + g);
        cpa16(dst + 32768, (const char*)g_ql + g);
    }
    LOAD_K(0, 0);
    cpa_commit();
    LOAD_K(1, TK);
    LOAD_V(0, 0);
    cpa_commit();

    float oacc[16][4];
    #pragma unroll
    for (int n = 0; n < 16; n++)
        #pragma unroll
        for (int c = 0; c < 4; c++) oacc[n][c] = 0.f;
    float sacc[8][4];
    uint32_t ph[4][4], pl[4][4];
    float m0r0 = 0.f, m0r1 = 0.f, lr0 = 0.f, lr1 = 0.f;

    // ---- S(0) standalone ----
    cpa_wait<1>();
    __syncthreads();
    ZERO_SACC();
    #pragma unroll
    for (int ks = 0; ks < 8; ks++) S_KS_BLOCK(ks, sb + OFF_K(0));

    {   // m0 from tile 0
        float mx0 = -CUDART_INF_F, mx1 = -CUDART_INF_F;
        #pragma unroll
        for (int n = 0; n < 8; n++) {
            mx0 = fmaxf(mx0, fmaxf(sacc[n][0], sacc[n][1]));
            mx1 = fmaxf(mx1, fmaxf(sacc[n][2], sacc[n][3]));
        }
        #pragma unroll
        for (int off = 1; off <= 2; off <<= 1) {
            mx0 = fmaxf(mx0, __shfl_xor_sync(0xffffffffu, mx0, off));
            mx1 = fmaxf(mx1, __shfl_xor_sync(0xffffffffu, mx1, off));
        }
        m0r0 = mx0; m0r1 = mx1;
    }
    SOFTMAX_ALL();
    cpa_wait<0>();
    __syncthreads();

    // ---- pipelined mainloop: phase t = [PV(t) || S(t+1)] ----
    #pragma unroll 1
    for (int t = 0; t < NT; t++) {
        if (t + 1 < NT) {
            if (t + 2 < NT) LOAD_K(t & 1, (t + 2) * TK);
            LOAD_V((t + 1) & 1, (t + 1) * TK);
            cpa_commit();
        }
        const uint32_t vb = sb + OFF_V(t & 1);
        if (t + 1 < NT) {
            const uint32_t kb = sb + OFF_K((t + 1) & 1);
            ZERO_SACC();
            #pragma unroll
            for (int u = 0; u < 8; u++) {
                S_KS_BLOCK(u, kb);
                PV_PIECE(vb, u >> 1, u & 1);
            }
            SOFTMAX_ALL();
        } else {
            #pragma unroll
            for (int u = 0; u < 8; u++) PV_PIECE(vb, u >> 1, u & 1);
        }
        cpa_wait<0>();
        __syncthreads();
    }

    // ---- epilogue: reduce l across quad, normalize, store ----
    #pragma unroll
    for (int off = 1; off <= 2; off <<= 1) {
        lr0 += __shfl_xor_sync(0xffffffffu, lr0, off);
        lr1 += __shfl_xor_sync(0xffffffffu, lr1, off);
    }
    float inv0 = 1.f / lr0, inv1 = 1.f / lr1;
    int qa = q0 + w * 16 + (lane >> 2);
    #pragma unroll
    for (int nn = 0; nn < 16; nn++) {
        int ch = nn * 8 + (lane & 3) * 2;
        out[((size_t)b * C_ + ch) * N_ + qa]           = oacc[nn][0] * inv0;
        out[((size_t)b * C_ + ch + 1) * N_ + qa]       = oacc[nn][1] * inv0;
        out[((size_t)b * C_ + ch) * N_ + qa + 8]       = oacc[nn][2] * inv1;
        out[((size_t)b * C_ + ch + 1) * N_ + qa + 8]   = oacc[nn][3] * inv1;
    }
}

// ---------------------------------------------------------------------------
extern "C" void kernel_launch(void* const* d_in, const int* in_sizes, int n_in,
                              void* d_out, int out_size)
{
    const float* x  = (const float*)d_in[0];
    const float* wq = (const float*)d_in[1];
    const float* bq = (const float*)d_in[2];
    const float* wk = (const float*)d_in[3];
    const float* bk = (const float*)d_in[4];
    const float* wv = (const float*)d_in[5];
    const float* bv = (const float*)d_in[6];
    float* out = (float*)d_out;

    cudaFuncSetAttribute(qkv_kernel,
                         cudaFuncAttributeMaxDynamicSharedMemorySize, 65536);
    cudaFuncSetAttribute(attn_kernel,
                         cudaFuncAttributeMaxDynamicSharedMemorySize, SMEM_ATTN);

    qkv_kernel<<<dim3(64, 6, 4), 256, 65536>>>(x, wq, bq, wk, bk, wv, bv);
    attn_kernel<<<dim3(N_ / TQ, B_), 256, SMEM_ATTN>>>(out);
}

// round 10
// speedup vs baseline: 1.0267x; 1.0267x over previous
#include <cuda_runtime.h>
#include <cuda_bf16.h>
#include <math_constants.h>
#include <cstdint>

#define B_ 4
#define C_ 128
#define N_ 4096
#define TQ 128           // queries per CTA
#define TK 64            // keys per iteration
#define NT (N_ / TK)     // 64 iterations

// bf16 hi/lo scratch, all token-major [B][N][C]
__device__ __nv_bfloat16 g_qh[B_*N_*C_], g_ql[B_*N_*C_];
__device__ __nv_bfloat16 g_kh[B_*N_*C_], g_kl[B_*N_*C_];
__device__ __nv_bfloat16 g_vh[B_*N_*C_], g_vl[B_*N_*C_];

// ---------------- helpers ----------------
__device__ __forceinline__ uint32_t smem_u32(const void* p) {
    uint32_t a;
    asm("{ .reg .u64 t; cvta.to.shared.u64 t, %1; cvt.u32.u64 %0, t; }"
        : "=r"(a) : "l"(p));
    return a;
}
__device__ __forceinline__ void cpa16(uint32_t dst, const void* src) {
    asm volatile("cp.async.cg.shared.global [%0], [%1], 16;" :: "r"(dst), "l"(src));
}
__device__ __forceinline__ void cpa_commit() {
    asm volatile("cp.async.commit_group;" ::: "memory");
}
template<int NG> __device__ __forceinline__ void cpa_wait() {
    asm volatile("cp.async.wait_group %0;" :: "n"(NG) : "memory");
}
__device__ __forceinline__ void ldsm4(uint32_t* r, uint32_t a) {
    asm volatile("ldmatrix.sync.aligned.m8n8.x4.shared.b16 {%0,%1,%2,%3}, [%4];"
                 : "=r"(r[0]), "=r"(r[1]), "=r"(r[2]), "=r"(r[3]) : "r"(a));
}
__device__ __forceinline__ void ldsm4t(uint32_t* r, uint32_t a) {
    asm volatile("ldmatrix.sync.aligned.m8n8.x4.trans.shared.b16 {%0,%1,%2,%3}, [%4];"
                 : "=r"(r[0]), "=r"(r[1]), "=r"(r[2]), "=r"(r[3]) : "r"(a));
}
__device__ __forceinline__ void mma16816(float* d, const uint32_t* a,
                                         const uint32_t* b) {
    asm volatile(
        "mma.sync.aligned.m16n8k16.row.col.f32.bf16.bf16.f32 "
        "{%0,%1,%2,%3}, {%4,%5,%6,%7}, {%8,%9}, {%0,%1,%2,%3};"
        : "+f"(d[0]), "+f"(d[1]), "+f"(d[2]), "+f"(d[3])
        : "r"(a[0]), "r"(a[1]), "r"(a[2]), "r"(a[3]), "r"(b[0]), "r"(b[1]));
}
__device__ __forceinline__ uint32_t pack_bf16(float lo, float hi) {
    uint32_t ul = (uint32_t)__bfloat16_as_ushort(__float2bfloat16_rn(lo));
    uint32_t uh = (uint32_t)__bfloat16_as_ushort(__float2bfloat16_rn(hi));
    return (uh << 16) | ul;
}
// 256B-row tiles (Q/K/V): 16B-chunk XOR swizzle, conflict-free ldmatrix.
__device__ __forceinline__ uint32_t swadr(uint32_t base, int row, int chunk) {
    return base + row * 256 + ((chunk ^ (row & 7)) << 4);
}
// 128B-row tiles (P): 8 chunks/row.
__device__ __forceinline__ uint32_t p_off(int row, int chunk) {
    return row * 128 + ((chunk ^ (row & 7)) << 4);
}
// barriers: bar 1 = CTA-wide phase sync; bar 8 = P-buffer handoff
__device__ __forceinline__ void bar1_sync() {
    asm volatile("bar.sync 1, 512;" ::: "memory");
}
__device__ __forceinline__ void bar8_sync() {
    asm volatile("bar.sync 8, 512;" ::: "memory");
}
__device__ __forceinline__ void bar8_arrive() {
    asm volatile("bar.arrive 8, 512;" ::: "memory");
}

// SMEM (bytes): QH 0..32K, QL 32K..64K
// K stage s: 64K + s*32K (KH +0, KL +16K)
// V stage s: 128K + s*32K (VH +0, VL +16K)
// P: 192K..224K (PH +0, PL +16K), 128 rows x 128 B
#define OFF_K(s) (65536 + (s) * 32768)
#define OFF_V(s) (131072 + (s) * 32768)
#define OFF_P    196608
#define SMEM_ATTN 229376

// ---------------------------------------------------------------------------
// QKV projection (fp32 SIMT GEMM) -> bf16 hi/lo token-major [B][N][C]
// ---------------------------------------------------------------------------
__global__ __launch_bounds__(256) void qkv_kernel(
    const float* __restrict__ x,
    const float* __restrict__ wq, const float* __restrict__ bq,
    const float* __restrict__ wk, const float* __restrict__ bk,
    const float* __restrict__ wv, const float* __restrict__ bv)
{
    extern __shared__ float sm[];
    float* Xs = sm;          // 128*64
    float* Ws = sm + 8192;   // 64*128

    const int tid = threadIdx.x;
    const int tx = tid & 15, ty = tid >> 4;
    const int ntile = blockIdx.x, otile = blockIdx.y, b = blockIdx.z;

    const float* w; const float* bias;
    __nv_bfloat16 *oh, *ol;
    if (otile < 2)      { w = wq; bias = bq; oh = g_qh; ol = g_ql; }
    else if (otile < 4) { w = wk; bias = bk; oh = g_kh; ol = g_kl; }
    else                { w = wv; bias = bv; oh = g_vh; ol = g_vl; }
    const int orow0 = (otile & 1) * 64;
    const int n0 = ntile * 64;

    #pragma unroll
    for (int p = 0; p < 32; p++) {
        int idx = tid + p * 256;
        Ws[idx] = w[(orow0 + (idx >> 7)) * C_ + (idx & 127)];
    }
    #pragma unroll
    for (int p = 0; p < 32; p++) {
        int idx = tid + p * 256;
        Xs[idx] = x[(b * C_ + (idx >> 6)) * N_ + n0 + (idx & 63)];
    }
    __syncthreads();

    float acc[4][4];
    #pragma unroll
    for (int i = 0; i < 4; i++)
        #pragma unroll
        for (int j = 0; j < 4; j++) acc[i][j] = 0.f;

    #pragma unroll 8
    for (int c = 0; c < 128; c++) {
        float4 xf = *(const float4*)&Xs[c * 64 + tx * 4];
        #pragma unroll
        for (int i = 0; i < 4; i++) {
            float wf = Ws[(ty * 4 + i) * 128 + c];
            acc[i][0] += wf * xf.x; acc[i][1] += wf * xf.y;
            acc[i][2] += wf * xf.z; acc[i][3] += wf * xf.w;
        }
    }

    float bb[4];
    #pragma unroll
    for (int i = 0; i < 4; i++) bb[i] = bias[orow0 + ty * 4 + i];

    #pragma unroll
    for (int j = 0; j < 4; j++) {
        int n = n0 + tx * 4 + j;
        __nv_bfloat16 h[4], l[4];
        #pragma unroll
        for (int i = 0; i < 4; i++) {
            float v = acc[i][j] + bb[i];
            h[i] = __float2bfloat16_rn(v);
            l[i] = __float2bfloat16_rn(v - __bfloat162float(h[i]));
        }
        size_t base = (size_t)(b * N_ + n) * C_ + orow0 + ty * 4;
        *(uint2*)&oh[base] = *(uint2*)h;
        *(uint2*)&ol[base] = *(uint2*)l;
    }
}

// ---------------------------------------------------------------------------
// Warp-specialized mma.sync flash attention, bf16x3.
// 512 threads: warps 0-7 = S (QK^T + softmax -> P smem),
//              warps 8-15 = PV (O += P V). Grid (N/128, B).
// Iteration shape (both roles): prefetch -> commit -> wait<1> -> bar1 ->
//                               compute -> bar1.
// The END bar1 prevents next-iteration prefetch from racing with this
// iteration's reads of the same double-buffer slot (the R9 bug).
// ---------------------------------------------------------------------------
__global__ __launch_bounds__(512, 1) void attn_kernel(float* __restrict__ out)
{
    extern __shared__ char smem[];
    const uint32_t sb = smem_u32(smem);
    const int tid = threadIdx.x;
    const int wid = tid >> 5, lane = tid & 31;
    const bool isS = wid < 8;
    const int b = blockIdx.y;
    const int q0 = blockIdx.x * TQ;

    // ---- prologue (all 512): Q hi/lo + K tile 0, one group ----
    #pragma unroll
    for (int i = 0; i < 4; i++) {
        int idx = tid + i * 512;              // 2048 chunks (128 rows x 16)
        int row = idx >> 4, ch = idx & 15;
        uint32_t dst = swadr(sb, row, ch);
        size_t g = ((size_t)(b * N_ + q0 + row) * C_) * 2 + ch * 16;
        cpa16(dst, (const char*)g_qh + g);
        cpa16(dst + 32768, (const char*)g_ql + g);
    }
    {
        const uint32_t kb = sb + OFF_K(0);
        #pragma unroll
        for (int i = 0; i < 2; i++) {
            int idx = tid + i * 512;          // 1024 chunks (64 rows x 16)
            int row = idx >> 4, ch = idx & 15;
            uint32_t dst = swadr(kb, row, ch);
            size_t g = ((size_t)(b * N_ + row) * C_) * 2 + ch * 16;
            cpa16(dst,         (const char*)g_kh + g);
            cpa16(dst + 16384, (const char*)g_kl + g);
        }
    }
    cpa_commit();

    if (isS) {
        // ================= S / softmax warps =================
        float sacc[8][4];
        float m0r0 = 0.f, m0r1 = 0.f, lr0 = 0.f, lr1 = 0.f;
        const int srow = wid << 4;
        const int r0 = srow + (lane >> 2);
        const int sh = (lane & 3) * 4;

        #pragma unroll 1
        for (int t = 0; t <= NT; t++) {
            // prefetch K(t+1) into slot (t+1)&1 (last read in iter t-1)
            if (t + 1 < NT) {
                const uint32_t kb = sb + OFF_K((t + 1) & 1);
                const int k0 = (t + 1) * TK;
                #pragma unroll
                for (int i = 0; i < 4; i++) {
                    int idx = tid + i * 256;
                    int row = idx >> 4, ch = idx & 15;
                    uint32_t dst = swadr(kb, row, ch);
                    size_t g = ((size_t)(b * N_ + k0 + row) * C_) * 2 + ch * 16;
                    cpa16(dst,         (const char*)g_kh + g);
                    cpa16(dst + 16384, (const char*)g_kl + g);
                }
            }
            cpa_commit();
            cpa_wait<1>();        // K(t) (and prologue) landed for this thread
            bar1_sync();          // ... and for every thread

            if (t < NT) {
                const uint32_t kb = sb + OFF_K(t & 1);
                #pragma unroll
                for (int n = 0; n < 8; n++) {
                    sacc[n][0] = 0.f; sacc[n][1] = 0.f;
                    sacc[n][2] = 0.f; sacc[n][3] = 0.f;
                }
                #pragma unroll
                for (int ks = 0; ks < 8; ks++) {
                    uint32_t qh4[4], ql4[4];
                    uint32_t qa = swadr(sb, srow + (lane & 15),
                                        ks * 2 + (lane >> 4));
                    ldsm4(qh4, qa); ldsm4(ql4, qa + 32768);
                    #pragma unroll
                    for (int np = 0; np < 4; np++) {
                        uint32_t khp[4], klp[4];
                        int krow = (2 * np + (lane >> 4)) * 8 + (lane & 7);
                        int kch = ks * 2 + ((lane >> 3) & 1);
                        uint32_t ka = swadr(kb, krow, kch);
                        ldsm4(khp, ka); ldsm4(klp, ka + 16384);
                        mma16816(sacc[2*np],   qh4, khp);
                        mma16816(sacc[2*np+1], qh4, khp + 2);
                        mma16816(sacc[2*np],   qh4, klp);
                        mma16816(sacc[2*np+1], qh4, klp + 2);
                        mma16816(sacc[2*np],   ql4, khp);
                        mma16816(sacc[2*np+1], ql4, khp + 2);
                    }
                }
                if (t == 0) {
                    float mx0 = -CUDART_INF_F, mx1 = -CUDART_INF_F;
                    #pragma unroll
                    for (int n = 0; n < 8; n++) {
                        mx0 = fmaxf(mx0, fmaxf(sacc[n][0], sacc[n][1]));
                        mx1 = fmaxf(mx1, fmaxf(sacc[n][2], sacc[n][3]));
                    }
                    #pragma unroll
                    for (int off = 1; off <= 2; off <<= 1) {
                        mx0 = fmaxf(mx0, __shfl_xor_sync(0xffffffffu, mx0, off));
                        mx1 = fmaxf(mx1, __shfl_xor_sync(0xffffffffu, mx1, off));
                    }
                    m0r0 = mx0; m0r1 = mx1;
                }
                bar8_sync();      // PV finished reading P(t-1)
                #pragma unroll
                for (int n = 0; n < 8; n++) {
                    float p0 = __expf(sacc[n][0] - m0r0);
                    float p1 = __expf(sacc[n][1] - m0r0);
                    float p2 = __expf(sacc[n][2] - m0r1);
                    float p3 = __expf(sacc[n][3] - m0r1);
                    lr0 += p0 + p1; lr1 += p2 + p3;
                    uint32_t h01 = pack_bf16(p0, p1);
                    uint32_t h23 = pack_bf16(p2, p3);
                    float h0 = __bfloat162float(__ushort_as_bfloat16((unsigned short)(h01 & 0xffff)));
                    float h1 = __bfloat162float(__ushort_as_bfloat16((unsigned short)(h01 >> 16)));
                    float h2 = __bfloat162float(__ushort_as_bfloat16((unsigned short)(h23 & 0xffff)));
                    float h3 = __bfloat162float(__ushort_as_bfloat16((unsigned short)(h23 >> 16)));
                    uint32_t l01 = pack_bf16(p0 - h0, p1 - h1);
                    uint32_t l23 = pack_bf16(p2 - h2, p3 - h3);
                    uint32_t o0 = OFF_P + (uint32_t)(r0 * 128) +
                                  (uint32_t)(((n ^ (r0 & 7)) << 4)) + sh;
                    uint32_t o1 = o0 + 8 * 128;
                    *(uint32_t*)(smem + o0) = h01;
                    *(uint32_t*)(smem + o1) = h23;
                    *(uint32_t*)(smem + o0 + 16384) = l01;
                    *(uint32_t*)(smem + o1 + 16384) = l23;
                }
            }
            bar1_sync();          // end barrier: protect slots from prefetch
        }
        // epilogue: publish l
        #pragma unroll
        for (int off = 1; off <= 2; off <<= 1) {
            lr0 += __shfl_xor_sync(0xffffffffu, lr0, off);
            lr1 += __shfl_xor_sync(0xffffffffu, lr1, off);
        }
        float* lsm = (float*)smem;   // Q region dead now
        if ((lane & 3) == 0) {
            lsm[r0] = lr0;
            lsm[r0 + 8] = lr1;
        }
        bar1_sync();
    } else {
        // ================= PV warps =================
        float oacc[16][4];
        #pragma unroll
        for (int n = 0; n < 16; n++)
            #pragma unroll
            for (int c = 0; c < 4; c++) oacc[n][c] = 0.f;
        uint32_t pfh[4][4], pfl[4][4];
        const int pw = wid - 8;
        const int ptid = tid - 256;

        #pragma unroll 1
        for (int t = 0; t <= NT; t++) {
            // prefetch V(t) into slot t&1 (last read in iter t-1)
            if (t < NT) {
                const uint32_t vbst = sb + OFF_V(t & 1);
                const int k0 = t * TK;
                #pragma unroll
                for (int i = 0; i < 4; i++) {
                    int idx = ptid + i * 256;
                    int row = idx >> 4, ch = idx & 15;
                    uint32_t dst = swadr(vbst, row, ch);
                    size_t g = ((size_t)(b * N_ + k0 + row) * C_) * 2 + ch * 16;
                    cpa16(dst,         (const char*)g_vh + g);
                    cpa16(dst + 16384, (const char*)g_vl + g);
                }
            }
            cpa_commit();
            cpa_wait<1>();        // V(t-1) + this thread's prologue landed
            bar1_sync();

            if (t > 0) {
                const int prow = pw * 16 + (lane & 15);
                #pragma unroll
                for (int kk = 0; kk < 4; kk++) {
                    uint32_t pa = sb + OFF_P + p_off(prow, kk * 2 + (lane >> 4));
                    ldsm4(pfh[kk], pa);
                    ldsm4(pfl[kk], pa + 16384);
                }
                if (t < NT) bar8_arrive();     // release P buffer to S
                const uint32_t vb = sb + OFF_V((t - 1) & 1);
                #pragma unroll
                for (int kk = 0; kk < 4; kk++) {
                    #pragma unroll
                    for (int np = 0; np < 8; np++) {
                        uint32_t vh[4], vl[4];
                        uint32_t va = swadr(vb, kk * 16 + (lane & 15),
                                            2 * np + (lane >> 4));
                        ldsm4t(vh, va);
                        ldsm4t(vl, va + 16384);
                        mma16816(oacc[2*np],   pfh[kk], vh);
                        mma16816(oacc[2*np+1], pfh[kk], vh + 2);
                        mma16816(oacc[2*np],   pfh[kk], vl);
                        mma16816(oacc[2*np+1], pfh[kk], vl + 2);
                        mma16816(oacc[2*np],   pfl[kk], vh);
                        mma16816(oacc[2*np+1], pfl[kk], vh + 2);
                    }
                }
            } else {
                bar8_arrive();    // nothing to read at t=0
            }
            bar1_sync();          // end barrier
        }
        // epilogue: normalize with l from S-warps, store
        bar1_sync();
        float* lsm = (float*)smem;
        const int rr0 = pw * 16 + (lane >> 2);
        float inv0 = 1.f / lsm[rr0];
        float inv1 = 1.f / lsm[rr0 + 8];
        int qa = q0 + rr0;
        #pragma unroll
        for (int nn = 0; nn < 16; nn++) {
            int ch = nn * 8 + (lane & 3) * 2;
            out[((size_t)b * C_ + ch) * N_ + qa]           = oacc[nn][0] * inv0;
            out[((size_t)b * C_ + ch + 1) * N_ + qa]       = oacc[nn][1] * inv0;
            out[((size_t)b * C_ + ch) * N_ + qa + 8]       = oacc[nn][2] * inv1;
            out[((size_t)b * C_ + ch + 1) * N_ + qa + 8]   = oacc[nn][3] * inv1;
        }
    }
}

// ---------------------------------------------------------------------------
extern "C" void kernel_launch(void* const* d_in, const int* in_sizes, int n_in,
                              void* d_out, int out_size)
{
    const float* x  = (const float*)d_in[0];
    const float* wq = (const float*)d_in[1];
    const float* bq = (const float*)d_in[2];
    const float* wk = (const float*)d_in[3];
    const float* bk = (const float*)d_in[4];
    const float* wv = (const float*)d_in[5];
    const float* bv = (const float*)d_in[6];
    float* out = (float*)d_out;

    cudaFuncSetAttribute(qkv_kernel,
                         cudaFuncAttributeMaxDynamicSharedMemorySize, 65536);
    cudaFuncSetAttribute(attn_kernel,
                         cudaFuncAttributeMaxDynamicSharedMemorySize, SMEM_ATTN);

    qkv_kernel<<<dim3(64, 6, 4), 256, 65536>>>(x, wq, bq, wk, bk, wv, bv);
    attn_kernel<<<dim3(N_ / TQ, B_), 512, SMEM_ATTN>>>(out);
}

// round 11
// speedup vs baseline: 1.1817x; 1.1510x over previous
#include <cuda_runtime.h>
#include <cuda_bf16.h>
#include <math_constants.h>
#include <cstdint>

#define B_ 4
#define C_ 128
#define N_ 4096
#define TQ 128           // queries per CTA
#define TK 64            // keys per iteration
#define NT (N_ / TK)     // 64 iterations

// bf16 hi/lo scratch, all token-major [B][N][C]
__device__ __nv_bfloat16 g_qh[B_*N_*C_], g_ql[B_*N_*C_];
__device__ __nv_bfloat16 g_kh[B_*N_*C_], g_kl[B_*N_*C_];
__device__ __nv_bfloat16 g_vh[B_*N_*C_], g_vl[B_*N_*C_];
// converted inputs: x channel-major [B][C][N]; w [3][128][128]
__device__ __nv_bfloat16 g_xh[B_*C_*N_], g_xl[B_*C_*N_];
__device__ __nv_bfloat16 g_wh[3*C_*C_],  g_wl[3*C_*C_];

// ---------------- helpers ----------------
__device__ __forceinline__ uint32_t smem_u32(const void* p) {
    uint32_t a;
    asm("{ .reg .u64 t; cvta.to.shared.u64 t, %1; cvt.u32.u64 %0, t; }"
        : "=r"(a) : "l"(p));
    return a;
}
__device__ __forceinline__ void cpa16(uint32_t dst, const void* src) {
    asm volatile("cp.async.cg.shared.global [%0], [%1], 16;" :: "r"(dst), "l"(src));
}
__device__ __forceinline__ void cpa_commit() {
    asm volatile("cp.async.commit_group;" ::: "memory");
}
template<int NG> __device__ __forceinline__ void cpa_wait() {
    asm volatile("cp.async.wait_group %0;" :: "n"(NG) : "memory");
}
__device__ __forceinline__ void ldsm4(uint32_t* r, uint32_t a) {
    asm volatile("ldmatrix.sync.aligned.m8n8.x4.shared.b16 {%0,%1,%2,%3}, [%4];"
                 : "=r"(r[0]), "=r"(r[1]), "=r"(r[2]), "=r"(r[3]) : "r"(a));
}
__device__ __forceinline__ void ldsm4t(uint32_t* r, uint32_t a) {
    asm volatile("ldmatrix.sync.aligned.m8n8.x4.trans.shared.b16 {%0,%1,%2,%3}, [%4];"
                 : "=r"(r[0]), "=r"(r[1]), "=r"(r[2]), "=r"(r[3]) : "r"(a));
}
__device__ __forceinline__ void mma16816(float* d, const uint32_t* a,
                                         const uint32_t* b) {
    asm volatile(
        "mma.sync.aligned.m16n8k16.row.col.f32.bf16.bf16.f32 "
        "{%0,%1,%2,%3}, {%4,%5,%6,%7}, {%8,%9}, {%0,%1,%2,%3};"
        : "+f"(d[0]), "+f"(d[1]), "+f"(d[2]), "+f"(d[3])
        : "r"(a[0]), "r"(a[1]), "r"(a[2]), "r"(a[3]), "r"(b[0]), "r"(b[1]));
}
__device__ __forceinline__ uint32_t pack_bf16(float lo, float hi) {
    uint32_t ul = (uint32_t)__bfloat16_as_ushort(__float2bfloat16_rn(lo));
    uint32_t uh = (uint32_t)__bfloat16_as_ushort(__float2bfloat16_rn(hi));
    return (uh << 16) | ul;
}
// 256B-row tiles: 16 chunks/row XOR swizzle
__device__ __forceinline__ uint32_t swadr(uint32_t base, int row, int chunk) {
    return base + row * 256 + ((chunk ^ (row & 7)) << 4);
}
// 128B-row tiles: 8 chunks/row
__device__ __forceinline__ uint32_t p_off(int row, int chunk) {
    return row * 128 + ((chunk ^ (row & 7)) << 4);
}

// ---------------------------------------------------------------------------
// cvt_kernel: fp32 -> bf16 hi/lo for x (2M elems) and the three w's (48K).
// grid 2096 x 256, float4 per thread.
// ---------------------------------------------------------------------------
__global__ __launch_bounds__(256) void cvt_kernel(
    const float* __restrict__ x,
    const float* __restrict__ wq, const float* __restrict__ wk,
    const float* __restrict__ wv)
{
    int idx = blockIdx.x * 256 + threadIdx.x;   // float4 index
    const float* src;
    __nv_bfloat16 *dh, *dl;
    int off;
    if (blockIdx.x < 2048) {                    // x: 524288 float4
        src = x; off = idx;
        dh = g_xh; dl = g_xl;
    } else {
        int j = idx - 2048 * 256;               // 0..12287
        int sel = j >> 12;                      // 4096 float4 per w
        src = (sel == 0) ? wq : (sel == 1) ? wk : wv;
        off = j & 4095;
        dh = g_wh + sel * (C_ * C_);
        dl = g_wl + sel * (C_ * C_);
        idx = off;
    }
    float4 v = ((const float4*)src)[idx];
    __nv_bfloat16 h[4], l[4];
    float vv[4] = {v.x, v.y, v.z, v.w};
    #pragma unroll
    for (int i = 0; i < 4; i++) {
        h[i] = __float2bfloat16_rn(vv[i]);
        l[i] = __float2bfloat16_rn(vv[i] - __bfloat162float(h[i]));
    }
    *(uint2*)&dh[idx * 4] = *(uint2*)h;
    *(uint2*)&dl[idx * 4] = *(uint2*)l;
}

// ---------------------------------------------------------------------------
// qkv_mma_kernel: out[n][o] = sum_c x[c][n] * w[o][c] + b[o], bf16x3 on
// tensor cores. Grid (64, 3, 4), 128 threads (4 warps).
// Warp w computes tokens [w*16, w*16+16) x all 128 outputs.
// A (tokens x c) via ldsm4.trans from x smem [c][token]; B = w[o][c] like
// attn's K tiles. Writes token-major bf16 hi/lo (attn's input contract).
// ---------------------------------------------------------------------------
__global__ __launch_bounds__(128) void qkv_mma_kernel(
    const float* __restrict__ bq, const float* __restrict__ bk,
    const float* __restrict__ bv)
{
    extern __shared__ char smem[];
    const uint32_t sb = smem_u32(smem);
    // XH 0..16K [c row][tok], XL 16K..32K, WH 32K..64K [o][c], WL 64K..96K
    const uint32_t XH = sb, XL = sb + 16384, WH = sb + 32768, WL = sb + 65536;

    const int tid = threadIdx.x;
    const int w = tid >> 5, lane = tid & 31;
    const int n0 = blockIdx.x * 64, ot = blockIdx.y, b = blockIdx.z;

    // x tile: 128 c-rows x 64 tokens (128 B/row), hi+lo
    #pragma unroll
    for (int i = 0; i < 8; i++) {
        int idx = tid + i * 128;               // 1024 chunks
        int row = idx >> 3, ch = idx & 7;
        uint32_t o = p_off(row, ch);
        size_t g = ((size_t)(b * C_ + row) * N_ + n0 + ch * 8) * 2;
        cpa16(XH + o, (const char*)g_xh + g);
        cpa16(XL + o, (const char*)g_xl + g);
    }
    // w tile: 128 o-rows x 128 c (256 B/row), hi+lo
    #pragma unroll
    for (int i = 0; i < 16; i++) {
        int idx = tid + i * 128;               // 2048 chunks
        int row = idx >> 4, ch = idx & 15;
        uint32_t o = swadr(0, row, ch);
        size_t g = ((size_t)ot * C_ * C_ + row * C_ + ch * 8) * 2;
        cpa16(WH + o, (const char*)g_wh + g);
        cpa16(WL + o, (const char*)g_wl + g);
    }
    cpa_commit();
    cpa_wait<0>();
    __syncthreads();

    float oacc[16][4];
    #pragma unroll
    for (int n = 0; n < 16; n++)
        #pragma unroll
        for (int c = 0; c < 4; c++) oacc[n][c] = 0.f;

    #pragma unroll
    for (int ks = 0; ks < 8; ks++) {
        uint32_t th[4], tl[4];
        uint32_t xa = p_off(ks * 16 + (lane & 15), 2 * w + (lane >> 4));
        ldsm4t(th, XH + xa);
        ldsm4t(tl, XL + xa);
        // trans-load perm {r0,r2,r1,r3} -> A-frag order
        uint32_t ah[4] = {th[0], th[2], th[1], th[3]};
        uint32_t al[4] = {tl[0], tl[2], tl[1], tl[3]};
        #pragma unroll
        for (int np = 0; np < 8; np++) {
            uint32_t wh4[4], wl4[4];
            uint32_t wa = swadr(0, (2 * np + (lane >> 4)) * 8 + (lane & 7),
                                ks * 2 + ((lane >> 3) & 1));
            ldsm4(wh4, WH + wa);
            ldsm4(wl4, WL + wa);
            mma16816(oacc[2*np],   ah, wh4);
            mma16816(oacc[2*np+1], ah, wh4 + 2);
            mma16816(oacc[2*np],   ah, wl4);
            mma16816(oacc[2*np+1], ah, wl4 + 2);
            mma16816(oacc[2*np],   al, wh4);
            mma16816(oacc[2*np+1], al, wh4 + 2);
        }
    }

    // epilogue: bias, hi/lo split, token-major store
    const float* bias = (ot == 0) ? bq : (ot == 1) ? bk : bv;
    __nv_bfloat16* oh = (ot == 0) ? g_qh : (ot == 1) ? g_kh : g_vh;
    __nv_bfloat16* ol = (ot == 0) ? g_ql : (ot == 1) ? g_kl : g_vl;
    const int row0 = w * 16 + (lane >> 2);
    const int row1 = row0 + 8;
    #pragma unroll
    for (int nn = 0; nn < 16; nn++) {
        int ch = nn * 8 + (lane & 3) * 2;
        float b0 = bias[ch], b1 = bias[ch + 1];
        float v0 = oacc[nn][0] + b0, v1 = oacc[nn][1] + b1;
        float v2 = oacc[nn][2] + b0, v3 = oacc[nn][3] + b1;
        uint32_t h01 = pack_bf16(v0, v1);
        uint32_t h23 = pack_bf16(v2, v3);
        float h0 = __bfloat162float(__ushort_as_bfloat16((unsigned short)(h01 & 0xffff)));
        float h1 = __bfloat162float(__ushort_as_bfloat16((unsigned short)(h01 >> 16)));
        float h2 = __bfloat162float(__ushort_as_bfloat16((unsigned short)(h23 & 0xffff)));
        float h3 = __bfloat162float(__ushort_as_bfloat16((unsigned short)(h23 >> 16)));
        uint32_t l01 = pack_bf16(v0 - h0, v1 - h1);
        uint32_t l23 = pack_bf16(v2 - h2, v3 - h3);
        size_t g0 = (size_t)(b * N_ + n0 + row0) * C_ + ch;
        size_t g1 = (size_t)(b * N_ + n0 + row1) * C_ + ch;
        *(uint32_t*)&oh[g0] = h01;
        *(uint32_t*)&oh[g1] = h23;
        *(uint32_t*)&ol[g0] = l01;
        *(uint32_t*)&ol[g1] = l23;
    }
}

// SMEM (attn): QH 0..32K, QL 32K..64K
// stage s at 64K + s*64K: KH +0, KL +16K, VH +32K, VL +48K
#define OFF_Q    0
#define OFF_KV   65536
#define STAGE_SZ 65536
#define SMEM_ATTN 196608
#define SMEM_QKV  98304

// ---------------------------------------------------------------------------
// mma.sync flash attention, bf16x3, softmax fused into PV loop (R5 verbatim).
// Grid (N/128, B), 256 threads (8 warps). Warp w owns query rows [w*16,w*16+16).
// ---------------------------------------------------------------------------
__global__ __launch_bounds__(256, 1) void attn_kernel(float* __restrict__ out)
{
    extern __shared__ char smem[];
    const uint32_t sb = smem_u32(smem);
    const int tid = threadIdx.x;
    const int w = tid >> 5, lane = tid & 31;
    const int b = blockIdx.y;
    const int q0 = blockIdx.x * TQ;

    const uint32_t sbQH = sb + OFF_Q;

    // ---- prologue: Q (hi/lo) + stage 0 (K,V hi/lo of tile 0) ----
    #pragma unroll
    for (int i = 0; i < 8; i++) {
        int idx = tid + i * 256;              // 2048 chunks
        int row = idx >> 4, ch = idx & 15;
        uint32_t dst = swadr(sbQH, row, ch);
        size_t g = ((size_t)(b * N_ + q0 + row) * C_) * 2 + ch * 16;
        cpa16(dst, (const char*)g_qh + g);
        cpa16(dst + 32768, (const char*)g_ql + g);
    }
    {
        const uint32_t st = sb + OFF_KV;
        #pragma unroll
        for (int i = 0; i < 4; i++) {
            int idx = tid + i * 256;          // 1024 chunks (64 rows x 16)
            int row = idx >> 4, ch = idx & 15;
            uint32_t dst = swadr(st, row, ch);
            size_t g = ((size_t)(b * N_ + row) * C_) * 2 + ch * 16;
            cpa16(dst,         (const char*)g_kh + g);
            cpa16(dst + 16384, (const char*)g_kl + g);
            cpa16(dst + 32768, (const char*)g_vh + g);
            cpa16(dst + 49152, (const char*)g_vl + g);
        }
    }
    cpa_commit();

    float oacc[16][4];
    #pragma unroll
    for (int n = 0; n < 16; n++)
        #pragma unroll
        for (int c = 0; c < 4; c++) oacc[n][c] = 0.f;
    float m0r0 = 0.f, m0r1 = 0.f, lr0 = 0.f, lr1 = 0.f;

    #pragma unroll 1
    for (int t = 0; t < NT; t++) {
        const uint32_t st = sb + OFF_KV + (t & 1) * STAGE_SZ;

        if (t + 1 < NT) {
            const uint32_t nst = sb + OFF_KV + ((t + 1) & 1) * STAGE_SZ;
            const int k0 = (t + 1) * TK;
            #pragma unroll
            for (int i = 0; i < 4; i++) {
                int idx = tid + i * 256;
                int row = idx >> 4, ch = idx & 15;
                uint32_t dst = swadr(nst, row, ch);
                size_t g = ((size_t)(b * N_ + k0 + row) * C_) * 2 + ch * 16;
                cpa16(dst,         (const char*)g_kh + g);
                cpa16(dst + 16384, (const char*)g_kl + g);
                cpa16(dst + 32768, (const char*)g_vh + g);
                cpa16(dst + 49152, (const char*)g_vl + g);
            }
            cpa_commit();
            cpa_wait<1>();
        } else {
            cpa_wait<0>();
        }
        __syncthreads();

        // ---- S = Q Kt^T, bf16x3, per-warp 16x64 ----
        float sacc[8][4];
        #pragma unroll
        for (int n = 0; n < 8; n++)
            #pragma unroll
            for (int c = 0; c < 4; c++) sacc[n][c] = 0.f;

        #pragma unroll
        for (int ks = 0; ks < 8; ks++) {
            uint32_t qh4[4], ql4[4];
            int qrow = w * 16 + (lane & 15);
            int qch = ks * 2 + (lane >> 4);
            uint32_t qa = swadr(sbQH, qrow, qch);
            ldsm4(qh4, qa);
            ldsm4(ql4, qa + 32768);
            #pragma unroll
            for (int np = 0; np < 4; np++) {
                uint32_t khp[4], klp[4];
                int krow = (2 * np + (lane >> 4)) * 8 + (lane & 7);
                int kch = ks * 2 + ((lane >> 3) & 1);
                uint32_t ka = swadr(st, krow, kch);
                ldsm4(khp, ka);
                ldsm4(klp, ka + 16384);
                mma16816(sacc[2*np],   qh4, khp);
                mma16816(sacc[2*np+1], qh4, khp + 2);
                mma16816(sacc[2*np],   qh4, klp);
                mma16816(sacc[2*np+1], qh4, klp + 2);
                mma16816(sacc[2*np],   ql4, khp);
                mma16816(sacc[2*np+1], ql4, khp + 2);
            }
        }

        // ---- fixed m0 from tile 0 ----
        if (t == 0) {
            float mx0 = -CUDART_INF_F, mx1 = -CUDART_INF_F;
            #pragma unroll
            for (int n = 0; n < 8; n++) {
                mx0 = fmaxf(mx0, fmaxf(sacc[n][0], sacc[n][1]));
                mx1 = fmaxf(mx1, fmaxf(sacc[n][2], sacc[n][3]));
            }
            #pragma unroll
            for (int off = 1; off <= 2; off <<= 1) {
                mx0 = fmaxf(mx0, __shfl_xor_sync(0xffffffffu, mx0, off));
                mx1 = fmaxf(mx1, __shfl_xor_sync(0xffffffffu, mx1, off));
            }
            m0r0 = mx0; m0r1 = mx1;
        }

        // ---- fused softmax + PV per 16-key chunk ----
        const uint32_t vst = st + 32768;
        #pragma unroll
        for (int kk = 0; kk < 4; kk++) {
            uint32_t ph[4], pl[4];
            #pragma unroll
            for (int half = 0; half < 2; half++) {
                int n = 2 * kk + half;
                float p0 = __expf(sacc[n][0] - m0r0);
                float p1 = __expf(sacc[n][1] - m0r0);
                float p2 = __expf(sacc[n][2] - m0r1);
                float p3 = __expf(sacc[n][3] - m0r1);
                lr0 += p0 + p1; lr1 += p2 + p3;
                uint32_t h01 = pack_bf16(p0, p1);
                uint32_t h23 = pack_bf16(p2, p3);
                float h0 = __bfloat162float(__ushort_as_bfloat16((unsigned short)(h01 & 0xffff)));
                float h1 = __bfloat162float(__ushort_as_bfloat16((unsigned short)(h01 >> 16)));
                float h2 = __bfloat162float(__ushort_as_bfloat16((unsigned short)(h23 & 0xffff)));
                float h3 = __bfloat162float(__ushort_as_bfloat16((unsigned short)(h23 >> 16)));
                ph[half * 2]     = h01;
                ph[half * 2 + 1] = h23;
                pl[half * 2]     = pack_bf16(p0 - h0, p1 - h1);
                pl[half * 2 + 1] = pack_bf16(p2 - h2, p3 - h3);
            }
            #pragma unroll
            for (int np = 0; np < 8; np++) {
                uint32_t vh[4], vl[4];
                uint32_t va = swadr(vst, kk * 16 + (lane & 15), 2 * np + (lane >> 4));
                ldsm4t(vh, va);
                ldsm4t(vl, va + 16384);
                mma16816(oacc[2*np],   ph, vh);
                mma16816(oacc[2*np+1], ph, vh + 2);
                mma16816(oacc[2*np],   ph, vl);
                mma16816(oacc[2*np+1], ph, vl + 2);
                mma16816(oacc[2*np],   pl, vh);
                mma16816(oacc[2*np+1], pl, vh + 2);
            }
        }
        __syncthreads();
    }

    // ---- epilogue: reduce l across quad, normalize, store ----
    #pragma unroll
    for (int off = 1; off <= 2; off <<= 1) {
        lr0 += __shfl_xor_sync(0xffffffffu, lr0, off);
        lr1 += __shfl_xor_sync(0xffffffffu, lr1, off);
    }
    float inv0 = 1.f / lr0, inv1 = 1.f / lr1;
    int qa = q0 + w * 16 + (lane >> 2);
    #pragma unroll
    for (int nn = 0; nn < 16; nn++) {
        int ch = nn * 8 + (lane & 3) * 2;
        out[((size_t)b * C_ + ch) * N_ + qa]           = oacc[nn][0] * inv0;
        out[((size_t)b * C_ + ch + 1) * N_ + qa]       = oacc[nn][1] * inv0;
        out[((size_t)b * C_ + ch) * N_ + qa + 8]       = oacc[nn][2] * inv1;
        out[((size_t)b * C_ + ch + 1) * N_ + qa + 8]   = oacc[nn][3] * inv1;
    }
}

// ---------------------------------------------------------------------------
extern "C" void kernel_launch(void* const* d_in, const int* in_sizes, int n_in,
                              void* d_out, int out_size)
{
    const float* x  = (const float*)d_in[0];
    const float* wq = (const float*)d_in[1];
    const float* bq = (const float*)d_in[2];
    const float* wk = (const float*)d_in[3];
    const float* bk = (const float*)d_in[4];
    const float* wv = (const float*)d_in[5];
    const float* bv = (const float*)d_in[6];
    float* out = (float*)d_out;

    cudaFuncSetAttribute(qkv_mma_kernel,
                         cudaFuncAttributeMaxDynamicSharedMemorySize, SMEM_QKV);
    cudaFuncSetAttribute(attn_kernel,
                         cudaFuncAttributeMaxDynamicSharedMemorySize, SMEM_ATTN);

    cvt_kernel<<<2096, 256>>>(x, wq, wk, wv);
    qkv_mma_kernel<<<dim3(64, 3, 4), 128, SMEM_QKV>>>(bq, bk, bv);
    attn_kernel<<<dim3(N_ / TQ, B_), 256, SMEM_ATTN>>>(out);
}